// round 17
// baseline (speedup 1.0000x reference)
#include <cuda_runtime.h>
#include <cuda_fp16.h>
#include <cstddef>

// Fastfood projection: out = (1/8192) * H * (G .* P(H * (B .* pad(x))))
// TWO rows per CTA, 256 threads, zero shuffles.
//
// Row-packing: every smem staging word is fp16x2 = (row0[e], row1[e]).
// The "pack bit" (row index) is in registers on both sides of every
// transpose, so ALL staging wavefronts (including the random permutation
// gather) are shared by two rows. Butterflies are fp32; only staging is fp16.
//
// Prep kernel (row-invariant, __device__ scratch):
//   g_slot16[e] : ushort word slot SF1(perm[e] & 4095)
//   g_Gs[e]     : G[e] * (1/8192)
//   g_Bmask[t]  : 16 sign bits of B[t*16..t*16+15]  (B is +-1 -> sign XOR)
//
// Pad symmetry: H1[e] == H1[e & 4095]; only lower 4096 materialized.
//
// FWHT#1 (12 bits, word-index e<4096, slot SF1(e)=e+4*(e>>5)+16*(e>>8)):
//   passes bits 0-3 / 4-7 / 8-11; layouts and bank-CF proofs as in R12:
//     T1 write: e = t*16+j          M1: e = 304-stride pattern
//     A1:       e = r*256+t
// FWHT#2 (13 bits, word-index e<8192, slot S4(e)=e+4*(e>>5)):
//   passes bits 0-4 / 5-9 / 10-12:
//     B  write: e = t*32+r  -> 36t+r        (8 x STS.128)
//     M  rw   : e = h8*1024+m*32+l -> 1152h8+36m+l  (banks l+const)
//     A  read : e = r*256+t -> 288r+t+4(t>>5)       (banks lane+4w+const)
// All patterns conflict-free on both sides (verified rounds 8-12).

#define NPAD       8192
#define IN_F       4096
#define SMEM_WORDS 9216   // S4 max 9211; SF1 max 4843

__device__ unsigned short g_slot16[NPAD];
__device__ float          g_Gs[NPAD];
__device__ unsigned int   g_Bmask[256];

__device__ __forceinline__ void bfly(float& a, float& b) {
    float x = a, y = b;
    a = x + y;
    b = x - y;
}

__device__ __forceinline__ unsigned int pack2(float lo, float hi) {
    __half2 h = __floats2half2_rn(lo, hi);
    return *reinterpret_cast<unsigned int*>(&h);
}
__device__ __forceinline__ float2 unpack2(unsigned int w) {
    __half2 h = *reinterpret_cast<__half2*>(&w);
    return __half22float2(h);
}

__global__ __launch_bounds__(256)
void fastfood_prep(const float* __restrict__ Bvec,
                   const float* __restrict__ Gvec,
                   const int*   __restrict__ perm)
{
    const int e = blockIdx.x * 256 + threadIdx.x;
    if (e < NPAD) {
        const int p = perm[e] & 4095;
        g_slot16[e] = (unsigned short)(p + ((p >> 5) << 2) + ((p >> 8) << 4));
        g_Gs[e]     = Gvec[e] * (1.0f / 8192.0f);
    }
    if (e < 256) {
        unsigned int m = 0;
#pragma unroll
        for (int j = 0; j < 16; ++j)
            if (Bvec[e * 16 + j] < 0.0f) m |= (1u << j);
        g_Bmask[e] = m;
    }
}

__global__ __launch_bounds__(256)
void fastfood_kernel(const float* __restrict__ x,
                     float*       __restrict__ out)
{
    __shared__ unsigned int s32[SMEM_WORDS];
    const int t    = threadIdx.x;
    const int row0 = blockIdx.x * 2;

    // ================= FWHT #1 : lower 4096 only, both rows =================
    {
        float a[16], b[16];
        {
            const float4* x0 = reinterpret_cast<const float4*>(x + (size_t)row0 * IN_F);
            const float4* x1 = reinterpret_cast<const float4*>(x + (size_t)(row0 + 1) * IN_F);
            const unsigned int bm = g_Bmask[t];
#pragma unroll
            for (int q = 0; q < 4; ++q) {
                float4 v0 = x0[t * 4 + q];
                float4 v1 = x1[t * 4 + q];
                const unsigned int s0 = ((bm >> (4 * q + 0)) & 1u) << 31;
                const unsigned int s1 = ((bm >> (4 * q + 1)) & 1u) << 31;
                const unsigned int s2 = ((bm >> (4 * q + 2)) & 1u) << 31;
                const unsigned int s3 = ((bm >> (4 * q + 3)) & 1u) << 31;
                a[4 * q + 0] = __uint_as_float(__float_as_uint(v0.x) ^ s0);
                a[4 * q + 1] = __uint_as_float(__float_as_uint(v0.y) ^ s1);
                a[4 * q + 2] = __uint_as_float(__float_as_uint(v0.z) ^ s2);
                a[4 * q + 3] = __uint_as_float(__float_as_uint(v0.w) ^ s3);
                b[4 * q + 0] = __uint_as_float(__float_as_uint(v1.x) ^ s0);
                b[4 * q + 1] = __uint_as_float(__float_as_uint(v1.y) ^ s1);
                b[4 * q + 2] = __uint_as_float(__float_as_uint(v1.z) ^ s2);
                b[4 * q + 3] = __uint_as_float(__float_as_uint(v1.w) ^ s3);
            }
        }
#pragma unroll
        for (int h = 1; h < 16; h <<= 1)
#pragma unroll
            for (int i = 0; i < 16; i += 2 * h)
#pragma unroll
                for (int j = i; j < i + h; ++j) { bfly(a[j], a[j + h]); bfly(b[j], b[j + h]); }

        // T1 write: SF1(t*16 + 4q + j), packed (row0, row1)
        const int base = 16 * t + 4 * (t >> 1) + 16 * (t >> 4);
#pragma unroll
        for (int q = 0; q < 4; ++q) {
            uint4 w;
            w.x = pack2(a[4 * q + 0], b[4 * q + 0]);
            w.y = pack2(a[4 * q + 1], b[4 * q + 1]);
            w.z = pack2(a[4 * q + 2], b[4 * q + 2]);
            w.w = pack2(a[4 * q + 3], b[4 * q + 3]);
            *reinterpret_cast<uint4*>(&s32[base + 4 * q]) = w;
        }
    }
    __syncthreads();

    {   // pass 2: layout M1 (regs = bits 4-7); in-place
        const int lo = t & 15, hi = t >> 4;
        const int base = 304 * hi + lo;
        float a[16], b[16];
#pragma unroll
        for (int m = 0; m < 16; ++m) {
            float2 f = unpack2(s32[base + 16 * m + 4 * (m >> 1)]);
            a[m] = f.x; b[m] = f.y;
        }
#pragma unroll
        for (int h = 1; h < 16; h <<= 1)
#pragma unroll
            for (int i = 0; i < 16; i += 2 * h)
#pragma unroll
                for (int j = i; j < i + h; ++j) { bfly(a[j], a[j + h]); bfly(b[j], b[j + h]); }
#pragma unroll
        for (int m = 0; m < 16; ++m)
            s32[base + 16 * m + 4 * (m >> 1)] = pack2(a[m], b[m]);
    }
    __syncthreads();

    {   // pass 3: layout A1 (regs = bits 8-11); in-place
        const int tA = t + 4 * (t >> 5);
        float a[16], b[16];
#pragma unroll
        for (int r = 0; r < 16; ++r) {
            float2 f = unpack2(s32[304 * r + tA]);
            a[r] = f.x; b[r] = f.y;
        }
#pragma unroll
        for (int h = 1; h < 16; h <<= 1)
#pragma unroll
            for (int i = 0; i < 16; i += 2 * h)
#pragma unroll
                for (int j = i; j < i + h; ++j) { bfly(a[j], a[j + h]); bfly(b[j], b[j + h]); }
#pragma unroll
        for (int r = 0; r < 16; ++r)
            s32[304 * r + tA] = pack2(a[r], b[r]);
    }
    __syncthreads();

    // ============ gather (one word serves both rows) + G, then FWHT#2 ============
    float va[32], vb[32];
    {
        const uint4*  sp = reinterpret_cast<const uint4*>(g_slot16);
        const float4* gp = reinterpret_cast<const float4*>(g_Gs);
#pragma unroll
        for (int q2 = 0; q2 < 4; ++q2) {
            uint4  u  = sp[t * 4 + q2];
            float4 ga = gp[t * 8 + 2 * q2];
            float4 gb = gp[t * 8 + 2 * q2 + 1];
            float2 f;
            f = unpack2(s32[u.x & 0xffffu]); va[8 * q2 + 0] = f.x * ga.x; vb[8 * q2 + 0] = f.y * ga.x;
            f = unpack2(s32[u.x >> 16]);     va[8 * q2 + 1] = f.x * ga.y; vb[8 * q2 + 1] = f.y * ga.y;
            f = unpack2(s32[u.y & 0xffffu]); va[8 * q2 + 2] = f.x * ga.z; vb[8 * q2 + 2] = f.y * ga.z;
            f = unpack2(s32[u.y >> 16]);     va[8 * q2 + 3] = f.x * ga.w; vb[8 * q2 + 3] = f.y * ga.w;
            f = unpack2(s32[u.z & 0xffffu]); va[8 * q2 + 4] = f.x * gb.x; vb[8 * q2 + 4] = f.y * gb.x;
            f = unpack2(s32[u.z >> 16]);     va[8 * q2 + 5] = f.x * gb.y; vb[8 * q2 + 5] = f.y * gb.y;
            f = unpack2(s32[u.w & 0xffffu]); va[8 * q2 + 6] = f.x * gb.z; vb[8 * q2 + 6] = f.y * gb.z;
            f = unpack2(s32[u.w >> 16]);     va[8 * q2 + 7] = f.x * gb.w; vb[8 * q2 + 7] = f.y * gb.w;
        }
    }

    // FWHT#2 pass 1: bits 0-4 (regs), both rows
#pragma unroll
    for (int h = 1; h < 32; h <<= 1)
#pragma unroll
        for (int i = 0; i < 32; i += 2 * h)
#pragma unroll
            for (int j = i; j < i + h; ++j) { bfly(va[j], va[j + h]); bfly(vb[j], vb[j + h]); }

    __syncthreads();   // all gather reads complete before overwriting s32

    {   // B write: S4(t*32 + 4q + j) = 36t + 4q + j
        const int base = 36 * t;
#pragma unroll
        for (int q = 0; q < 8; ++q) {
            uint4 w;
            w.x = pack2(va[4 * q + 0], vb[4 * q + 0]);
            w.y = pack2(va[4 * q + 1], vb[4 * q + 1]);
            w.z = pack2(va[4 * q + 2], vb[4 * q + 2]);
            w.w = pack2(va[4 * q + 3], vb[4 * q + 3]);
            *reinterpret_cast<uint4*>(&s32[base + 4 * q]) = w;
        }
    }
    __syncthreads();

    {   // pass 2: layout M (regs = bits 5-9); in-place
        const int l = t & 31, h8 = t >> 5;
        const int base = 1152 * h8 + l;
#pragma unroll
        for (int m = 0; m < 32; ++m) {
            float2 f = unpack2(s32[base + 36 * m]);
            va[m] = f.x; vb[m] = f.y;
        }
#pragma unroll
        for (int h = 1; h < 32; h <<= 1)
#pragma unroll
            for (int i = 0; i < 32; i += 2 * h)
#pragma unroll
                for (int j = i; j < i + h; ++j) { bfly(va[j], va[j + h]); bfly(vb[j], vb[j + h]); }
#pragma unroll
        for (int m = 0; m < 32; ++m)
            s32[base + 36 * m] = pack2(va[m], vb[m]);
    }
    __syncthreads();

    {   // pass 3: layout A (regs = bits 8-12; butterflies bits 10-12), then store
        const int tA = t + 4 * (t >> 5);
#pragma unroll
        for (int r = 0; r < 32; ++r) {
            float2 f = unpack2(s32[288 * r + tA]);
            va[r] = f.x; vb[r] = f.y;
        }
#pragma unroll
        for (int h = 4; h < 32; h <<= 1)
#pragma unroll
            for (int i = 0; i < 32; i += 2 * h)
#pragma unroll
                for (int j = i; j < i + h; ++j) { bfly(va[j], va[j + h]); bfly(vb[j], vb[j + h]); }

        float* o0 = out + (size_t)row0 * NPAD + t;
        float* o1 = o0 + NPAD;
#pragma unroll
        for (int r = 0; r < 32; ++r) o0[r * 256] = va[r];
#pragma unroll
        for (int r = 0; r < 32; ++r) o1[r * 256] = vb[r];
    }
}

extern "C" void kernel_launch(void* const* d_in, const int* in_sizes, int n_in,
                              void* d_out, int out_size)
{
    const float* x    = (const float*)d_in[0];
    const float* Bv   = (const float*)d_in[1];
    const float* Gv   = (const float*)d_in[2];
    const int*   perm = (const int*)d_in[3];
    float*       out  = (float*)d_out;

    const int rows = in_sizes[0] / IN_F;   // 8192

    fastfood_prep<<<(NPAD + 255) / 256, 256>>>(Bv, Gv, perm);
    fastfood_kernel<<<rows / 2, 256>>>(x, out);
}